// round 1
// baseline (speedup 1.0000x reference)
#include <cuda_runtime.h>

#define BN 64
#define BD 512
#define BB 16

// Scratch (static device globals — no allocations)
__device__ int   d_tbl[4096];              // packed per-(i,j) structure table
__device__ float d_kq[BB * 64 * 1024];     // [b][n][0:512]=m_k, [512:1024]=m_q
__device__ float d_factor[BB * 4096];      // 1 + softmax weights

// Sparse-table level offsets for window sizes 2^l, l=0..6 over length-64 rows.
// level l has 65 - 2^l entries. Flat layout size = 328.
__device__ __forceinline__ int pack_entry(int a, int b) {
    int len = b - a;                 // window length, 1..64
    int l = 31 - __clz(len);         // floor(log2(len))
    const int off[7] = {0, 64, 127, 188, 245, 294, 327};
    int i1 = off[l] + a;
    int i2 = off[l] + b - (1 << l);
    return i1 | (i2 << 10) | 0x40000000;
}

// ---------------------------------------------------------------------------
// Kernel 0: build the structure table (replicates SparseMaxPool.__init__ +
// pooling-window composition). Serial on one thread — ~2K ops, trivial.
// ---------------------------------------------------------------------------
__global__ void prep_kernel() {
    if (threadIdx.x != 0) return;
    for (int i = 0; i < 4096; i++) d_tbl[i] = -1;
    int lo[64], hi[64];
    for (int p = 0; p < 64; p++) {
        lo[p] = p; hi[p] = p + 1;
        d_tbl[p * 64 + p] = pack_entry(p, p + 1);   // diagonal
    }
    int len = 64, stride = 1, offset = 0;
    const int counts[3] = {15, 8, 8};
    for (int ci = 0; ci < 3; ci++) {
        for (int t = 0; t < counts[ci]; t++) {
            offset += stride;
            int k = (ci == 0 || t > 0) ? 2 : 3;
            int s = (k == 2) ? 1 : 2;
            int nl = (len - k) / s + 1;
            for (int p = 0; p < nl; p++) {
                int a = lo[p * s];
                int b = hi[p * s + k - 1];
                lo[p] = a; hi[p] = b;
                int i = p * stride, j = i + offset;
                d_tbl[i * 64 + j] = pack_entry(a, b);
            }
            len = nl;
        }
        stride *= 2;
    }
}

// ---------------------------------------------------------------------------
// Kernel 1: m_k / m_q GEMM.  out[b,n,o] = sum_dd x[b,dd,n] * W[o,dd] + bias[o]
// o<512 -> w_v/b_v ; o>=512 -> w_c[0:512]/b_c[0:512].
// Grid (16 o-tiles, 16 b), 256 threads, 64x64 tile, 4x4 per thread.
// ---------------------------------------------------------------------------
__global__ __launch_bounds__(256) void gemm_kernel(
    const float* __restrict__ x, const float* __restrict__ w_v,
    const float* __restrict__ b_v, const float* __restrict__ w_c,
    const float* __restrict__ b_c)
{
    int b = blockIdx.y;
    int o0 = blockIdx.x * 64;
    const float* W; const float* bias;
    if (o0 < 512) { W = w_v + (size_t)o0 * 512;          bias = b_v + o0; }
    else          { W = w_c + (size_t)(o0 - 512) * 512;  bias = b_c + (o0 - 512); }
    const float* xb = x + (size_t)b * BD * BN;

    __shared__ float As[16][64];   // [kk][n]  (F tile)
    __shared__ float Ws[16][68];   // [kk][o]  (W tile, transposed, padded)

    int tid = threadIdx.x;
    int tx = tid & 15, ty = tid >> 4;
    float acc[4][4];
#pragma unroll
    for (int r = 0; r < 4; r++)
#pragma unroll
        for (int c = 0; c < 4; c++) acc[r][c] = 0.f;

    for (int kt = 0; kt < 512; kt += 16) {
#pragma unroll
        for (int it = 0; it < 4; it++) {
            int e = tid + it * 256;
            int dd = e >> 6, n = e & 63;
            As[dd][n] = xb[(size_t)(kt + dd) * 64 + n];   // coalesced
        }
        {
            int o = tid >> 2, c4 = tid & 3;
            float4 v = *(const float4*)(W + (size_t)o * 512 + kt + c4 * 4);
            Ws[c4 * 4 + 0][o] = v.x; Ws[c4 * 4 + 1][o] = v.y;
            Ws[c4 * 4 + 2][o] = v.z; Ws[c4 * 4 + 3][o] = v.w;
        }
        __syncthreads();
#pragma unroll
        for (int kk = 0; kk < 16; kk++) {
            float4 a4 = *(const float4*)&As[kk][ty * 4];
            float4 b4 = *(const float4*)&Ws[kk][tx * 4];
            float av[4] = {a4.x, a4.y, a4.z, a4.w};
            float bw[4] = {b4.x, b4.y, b4.z, b4.w};
#pragma unroll
            for (int r = 0; r < 4; r++)
#pragma unroll
                for (int c = 0; c < 4; c++)
                    acc[r][c] += av[r] * bw[c];
        }
        __syncthreads();
    }
    float4 bias4 = *(const float4*)(bias + tx * 4);
    float bb[4] = {bias4.x, bias4.y, bias4.z, bias4.w};
#pragma unroll
    for (int r = 0; r < 4; r++) {
        float4 o4;
        o4.x = acc[r][0] + bb[0]; o4.y = acc[r][1] + bb[1];
        o4.z = acc[r][2] + bb[2]; o4.w = acc[r][3] + bb[3];
        *(float4*)&d_kq[(size_t)b * 65536 + (size_t)(ty * 4 + r) * 1024 + o0 + tx * 4] = o4;
    }
}

// ---------------------------------------------------------------------------
// Kernel 2: m2m = m_k @ m_q^T / 8, row softmax, factor = 1 + w.
// Grid (4 row-tiles, 16 b), 256 threads. 16x64 output per block, K=512.
// ---------------------------------------------------------------------------
__global__ __launch_bounds__(256) void attn_kernel() {
    int b = blockIdx.y;
    int n0 = blockIdx.x * 16;
    __shared__ float Sk[16][33];
    __shared__ float Sq[32][68];
    __shared__ float sm[16][68];
    __shared__ float red[16];
    int tid = threadIdx.x;
    int tr = tid >> 4, tc = tid & 15;
    float acc[4] = {0, 0, 0, 0};
    const float* kq = d_kq + (size_t)b * 65536;

    for (int kt = 0; kt < 512; kt += 32) {
#pragma unroll
        for (int it = 0; it < 2; it++) {
            int u = tid + it * 256;
            int r = u >> 5, kk = u & 31;
            Sk[r][kk] = kq[(size_t)(n0 + r) * 1024 + kt + kk];
        }
#pragma unroll
        for (int it = 0; it < 2; it++) {
            int u = tid + it * 256;
            int m = u >> 3, c4 = u & 7;
            float4 v = *(const float4*)(kq + (size_t)m * 1024 + 512 + kt + c4 * 4);
            Sq[c4 * 4 + 0][m] = v.x; Sq[c4 * 4 + 1][m] = v.y;
            Sq[c4 * 4 + 2][m] = v.z; Sq[c4 * 4 + 3][m] = v.w;
        }
        __syncthreads();
#pragma unroll
        for (int kk = 0; kk < 32; kk++) {
            float a = Sk[tr][kk];
            float4 b4 = *(const float4*)&Sq[kk][tc * 4];
            acc[0] += a * b4.x; acc[1] += a * b4.y;
            acc[2] += a * b4.z; acc[3] += a * b4.w;
        }
        __syncthreads();
    }
#pragma unroll
    for (int c = 0; c < 4; c++) sm[tr][tc * 4 + c] = acc[c] * 0.125f;
    __syncthreads();
    if (tid < 16) {
        float mx = -1e30f;
        for (int m = 0; m < 64; m++) mx = fmaxf(mx, sm[tid][m]);
        red[tid] = mx;
    }
    __syncthreads();
    float mx = red[tr];
    float e[4];
#pragma unroll
    for (int c = 0; c < 4; c++) {
        e[c] = __expf(sm[tr][tc * 4 + c] - mx);
        sm[tr][tc * 4 + c] = e[c];
    }
    __syncthreads();
    if (tid < 16) {
        float s = 0.f;
        for (int m = 0; m < 64; m++) s += sm[tid][m];
        red[tid] = 1.f / s;
    }
    __syncthreads();
    float inv = red[tr];
#pragma unroll
    for (int c = 0; c < 4; c++)
        d_factor[(size_t)b * 4096 + (size_t)(n0 + tr) * 64 + tc * 4 + c] = 1.f + e[c] * inv;
}

// ---------------------------------------------------------------------------
// Kernel 3: main store kernel. Block = (b, 8 consecutive d).
// Builds per-d sparse max table in smem, then streams boundary/local/content.
// ---------------------------------------------------------------------------
__global__ __launch_bounds__(256) void main_kernel(
    const float* __restrict__ x, float* __restrict__ out)
{
    int b  = blockIdx.y;
    int d0 = blockIdx.x * 8;
    __shared__ float lev[8][336];
    int tid = threadIdx.x;

    for (int u = tid; u < 512; u += 256) {
        int dg = u >> 6, n = u & 63;
        lev[dg][n] = x[((size_t)(b * BD + d0 + dg)) * 64 + n];
    }
    __syncthreads();
    const int offA[7] = {0, 64, 127, 188, 245, 294, 327};
#pragma unroll
    for (int l = 1; l < 7; l++) {
        int cnt = 65 - (1 << l);
        int half = 1 << (l - 1);
        for (int u = tid; u < 8 * cnt; u += 256) {
            int dg = u / cnt, p = u - dg * cnt;
            lev[dg][offA[l] + p] =
                fmaxf(lev[dg][offA[l - 1] + p], lev[dg][offA[l - 1] + p + half]);
        }
        __syncthreads();
    }

    const size_t mapsz = (size_t)BB * BD * 4096;   // elements per map
    if (blockIdx.x == 0) {
        for (int u = tid; u < 4096; u += 256)
            out[3 * mapsz + (size_t)b * 4096 + u] = (d_tbl[u] >= 0) ? 1.f : 0.f;
    }

    const int4*   tblv = (const int4*)d_tbl;
    const float4* facv = (const float4*)(d_factor + (size_t)b * 4096);
    float4* outB = (float4*)out + ((size_t)(b * BD + d0)) * 1024;
    float4* outL = outB + mapsz / 4;
    float4* outC = outB + mapsz / 2;

#pragma unroll
    for (int it = 0; it < 4; it++) {
        int q = tid + it * 256;          // quad index: covers elements 4q..4q+3
        int4 t4 = tblv[q];
        int i  = q >> 4;                 // row
        int j0 = (q & 15) << 2;          // first col of quad
        bool allzero = ((t4.x & t4.y & t4.z & t4.w) < 0);
        if (allzero) {
            float4 z = make_float4(0.f, 0.f, 0.f, 0.f);
#pragma unroll
            for (int dg = 0; dg < 8; dg++) {
                size_t o = (size_t)dg * 1024 + q;
                __stcs(&outB[o], z); __stcs(&outL[o], z); __stcs(&outC[o], z);
            }
            continue;
        }
        float4 f4 = facv[q];
        float fs[4] = {f4.x, f4.y, f4.z, f4.w};
        int   ts[4] = {t4.x, t4.y, t4.z, t4.w};
#pragma unroll
        for (int dg = 0; dg < 8; dg++) {
            const float* L = lev[dg];
            float xi = L[i];
            float bo[4], lc[4], co[4];
#pragma unroll
            for (int c = 0; c < 4; c++) {
                int t = ts[c];
                if (t < 0) { bo[c] = 0.f; lc[c] = 0.f; co[c] = 0.f; }
                else {
                    int j = j0 + c;
                    float xj = L[j];
                    float xk = L[(i + j) >> 1];
                    float f  = fs[c];
                    bo[c] = (xi + xj) * 0.5f * f;
                    lc[c] = (xi + xj + 0.5f * xk) * (1.f / 2.5f) * f;
                    co[c] = fmaxf(L[t & 1023], L[(t >> 10) & 1023]) * f;
                }
            }
            size_t o = (size_t)dg * 1024 + q;
            __stcs(&outB[o], make_float4(bo[0], bo[1], bo[2], bo[3]));
            __stcs(&outL[o], make_float4(lc[0], lc[1], lc[2], lc[3]));
            __stcs(&outC[o], make_float4(co[0], co[1], co[2], co[3]));
        }
    }
}

// ---------------------------------------------------------------------------
extern "C" void kernel_launch(void* const* d_in, const int* in_sizes, int n_in,
                              void* d_out, int out_size) {
    const float* x   = (const float*)d_in[0];
    const float* w_c = (const float*)d_in[1];
    const float* b_c = (const float*)d_in[2];
    const float* w_v = (const float*)d_in[3];
    const float* b_v = (const float*)d_in[4];
    float* out = (float*)d_out;

    prep_kernel<<<1, 32>>>();
    gemm_kernel<<<dim3(16, 16), 256>>>(x, w_v, b_v, w_c, b_c);
    attn_kernel<<<dim3(4, 16), 256>>>();
    main_kernel<<<dim3(64, 16), 256>>>(x, out);
}

// round 4
// speedup vs baseline: 1.8659x; 1.8659x over previous
#include <cuda_runtime.h>
#include <cstdint>

#define BN 64
#define BD 512
#define BB 16

// ---------------------------------------------------------------------------
// Compile-time structure table (no prep kernel).
// Entry = i1 | (i2<<10) | 0x40000000 for masked (i,j): content = max(L[i1],L[i2])
// over a 7-level sparse max table; -1 for unmasked.
// ---------------------------------------------------------------------------
struct TblT { int v[4096]; };

constexpr int ilog2c(int v) { int l = 0; while ((1 << (l + 1)) <= v) l++; return l; }

constexpr int pack_entry_c(int a, int b) {
    int len = b - a;
    int l = ilog2c(len);
    const int off[7] = {0, 64, 127, 188, 245, 294, 327};
    int i1 = off[l] + a;
    int i2 = off[l] + b - (1 << l);
    return i1 | (i2 << 10) | 0x40000000;
}

constexpr TblT make_tbl() {
    TblT t{};
    for (int i = 0; i < 4096; i++) t.v[i] = -1;
    int lo[64] = {}, hi[64] = {};
    for (int p = 0; p < 64; p++) {
        lo[p] = p; hi[p] = p + 1;
        t.v[p * 64 + p] = pack_entry_c(p, p + 1);
    }
    int len = 64, stride = 1, offset = 0;
    const int counts[3] = {15, 8, 8};
    for (int ci = 0; ci < 3; ci++) {
        for (int tt = 0; tt < counts[ci]; tt++) {
            offset += stride;
            int k = (ci == 0 || tt > 0) ? 2 : 3;
            int s = (k == 2) ? 1 : 2;
            int nl = (len - k) / s + 1;
            for (int p = 0; p < nl; p++) {
                int a = lo[p * s];
                int b = hi[p * s + k - 1];
                lo[p] = a; hi[p] = b;
                int i = p * stride, j = i + offset;
                t.v[i * 64 + j] = pack_entry_c(a, b);
            }
            len = nl;
        }
        stride *= 2;
    }
    return t;
}

constexpr TblT HOST_TBL = make_tbl();
__device__ const TblT g_tbl = HOST_TBL;

// Scratch (static device globals — no allocations)
__device__ float d_kq[BB * 64 * 1024];     // [b][n][0:512]=m_k, [512:1024]=m_q
__device__ float d_factor[BB * 4096];      // 1 + softmax weights

// ---------------------------------------------------------------------------
// Kernel 1: m_k / m_q GEMM.  out[b,n,o] = sum_dd x[b,dd,n] * W[o,dd] + bias[o]
// ---------------------------------------------------------------------------
__global__ __launch_bounds__(256) void gemm_kernel(
    const float* __restrict__ x, const float* __restrict__ w_v,
    const float* __restrict__ b_v, const float* __restrict__ w_c,
    const float* __restrict__ b_c)
{
    int b = blockIdx.y;
    int o0 = blockIdx.x * 64;
    const float* W; const float* bias;
    if (o0 < 512) { W = w_v + (size_t)o0 * 512;          bias = b_v + o0; }
    else          { W = w_c + (size_t)(o0 - 512) * 512;  bias = b_c + (o0 - 512); }
    const float* xb = x + (size_t)b * BD * BN;

    __shared__ float As[16][64];
    __shared__ float Ws[16][68];

    int tid = threadIdx.x;
    int tx = tid & 15, ty = tid >> 4;
    float acc[4][4];
#pragma unroll
    for (int r = 0; r < 4; r++)
#pragma unroll
        for (int c = 0; c < 4; c++) acc[r][c] = 0.f;

    for (int kt = 0; kt < 512; kt += 16) {
#pragma unroll
        for (int it = 0; it < 4; it++) {
            int e = tid + it * 256;
            int dd = e >> 6, n = e & 63;
            As[dd][n] = xb[(size_t)(kt + dd) * 64 + n];
        }
        {
            int o = tid >> 2, c4 = tid & 3;
            float4 v = *(const float4*)(W + (size_t)o * 512 + kt + c4 * 4);
            Ws[c4 * 4 + 0][o] = v.x; Ws[c4 * 4 + 1][o] = v.y;
            Ws[c4 * 4 + 2][o] = v.z; Ws[c4 * 4 + 3][o] = v.w;
        }
        __syncthreads();
#pragma unroll
        for (int kk = 0; kk < 16; kk++) {
            float4 a4 = *(const float4*)&As[kk][ty * 4];
            float4 b4 = *(const float4*)&Ws[kk][tx * 4];
            float av[4] = {a4.x, a4.y, a4.z, a4.w};
            float bw[4] = {b4.x, b4.y, b4.z, b4.w};
#pragma unroll
            for (int r = 0; r < 4; r++)
#pragma unroll
                for (int c = 0; c < 4; c++)
                    acc[r][c] += av[r] * bw[c];
        }
        __syncthreads();
    }
    float4 bias4 = *(const float4*)(bias + tx * 4);
    float bb[4] = {bias4.x, bias4.y, bias4.z, bias4.w};
#pragma unroll
    for (int r = 0; r < 4; r++) {
        float4 o4;
        o4.x = acc[r][0] + bb[0]; o4.y = acc[r][1] + bb[1];
        o4.z = acc[r][2] + bb[2]; o4.w = acc[r][3] + bb[3];
        *(float4*)&d_kq[(size_t)b * 65536 + (size_t)(ty * 4 + r) * 1024 + o0 + tx * 4] = o4;
    }
}

// ---------------------------------------------------------------------------
// Kernel 2: m2m = m_k @ m_q^T / 8, row softmax, factor = 1 + w.
// ---------------------------------------------------------------------------
__global__ __launch_bounds__(256) void attn_kernel() {
    int b = blockIdx.y;
    int n0 = blockIdx.x * 16;
    __shared__ float Sk[16][33];
    __shared__ float Sq[32][68];
    __shared__ float sm[16][68];
    __shared__ float red[16];
    int tid = threadIdx.x;
    int tr = tid >> 4, tc = tid & 15;
    float acc[4] = {0, 0, 0, 0};
    const float* kq = d_kq + (size_t)b * 65536;

    for (int kt = 0; kt < 512; kt += 32) {
#pragma unroll
        for (int it = 0; it < 2; it++) {
            int u = tid + it * 256;
            int r = u >> 5, kk = u & 31;
            Sk[r][kk] = kq[(size_t)(n0 + r) * 1024 + kt + kk];
        }
#pragma unroll
        for (int it = 0; it < 2; it++) {
            int u = tid + it * 256;
            int m = u >> 3, c4 = u & 7;
            float4 v = *(const float4*)(kq + (size_t)m * 1024 + 512 + kt + c4 * 4);
            Sq[c4 * 4 + 0][m] = v.x; Sq[c4 * 4 + 1][m] = v.y;
            Sq[c4 * 4 + 2][m] = v.z; Sq[c4 * 4 + 3][m] = v.w;
        }
        __syncthreads();
#pragma unroll
        for (int kk = 0; kk < 32; kk++) {
            float a = Sk[tr][kk];
            float4 b4 = *(const float4*)&Sq[kk][tc * 4];
            acc[0] += a * b4.x; acc[1] += a * b4.y;
            acc[2] += a * b4.z; acc[3] += a * b4.w;
        }
        __syncthreads();
    }
#pragma unroll
    for (int c = 0; c < 4; c++) sm[tr][tc * 4 + c] = acc[c] * 0.125f;
    __syncthreads();
    if (tid < 16) {
        float mx = -1e30f;
        for (int m = 0; m < 64; m++) mx = fmaxf(mx, sm[tid][m]);
        red[tid] = mx;
    }
    __syncthreads();
    float mx = red[tr];
    float e[4];
#pragma unroll
    for (int c = 0; c < 4; c++) {
        e[c] = __expf(sm[tr][tc * 4 + c] - mx);
        sm[tr][tc * 4 + c] = e[c];
    }
    __syncthreads();
    if (tid < 16) {
        float s = 0.f;
        for (int m = 0; m < 64; m++) s += sm[tid][m];
        red[tid] = 1.f / s;
    }
    __syncthreads();
    float inv = red[tr];
#pragma unroll
    for (int c = 0; c < 4; c++)
        d_factor[(size_t)b * 4096 + (size_t)(n0 + tr) * 64 + tc * 4 + c] = 1.f + e[c] * inv;
}

// ---------------------------------------------------------------------------
// Kernel 3: one block per (b, d). Row processed in 4 chunks of 1024 elements,
// double-buffered in smem; each chunk drains via three 4 KB cp.async.bulk
// stores in one bulk group. Dynamic smem: 2*3*1024*4 = 24 KB (< 48 KB limit).
// ---------------------------------------------------------------------------
#define SMEM_MAIN_BYTES (2 * 3 * 1024 * 4)

__global__ __launch_bounds__(256) void main_kernel(
    const float* __restrict__ x, float* __restrict__ out)
{
    __shared__ float lev[352];
    extern __shared__ float smb[];   // [2][3][1024]

    int b = blockIdx.y;
    int d = blockIdx.x;
    int tid = threadIdx.x;

    // Load the x row and build the 7-level sparse max table.
    if (tid < 64) lev[tid] = x[((size_t)(b * BD + d)) * 64 + tid];
    __syncthreads();
    const int offA[7] = {0, 64, 127, 188, 245, 294, 327};
#pragma unroll
    for (int l = 1; l < 7; l++) {
        int cnt = 65 - (1 << l);
        int half = 1 << (l - 1);
        if (tid < cnt)
            lev[offA[l] + tid] = fmaxf(lev[offA[l - 1] + tid],
                                       lev[offA[l - 1] + tid + half]);
        __syncthreads();
    }

    const size_t mapsz = (size_t)BB * BD * 4096;
    const int4*   tblv = (const int4*)g_tbl.v;
    const float4* facv = (const float4*)(d_factor + (size_t)b * 4096);
    float* maskp = out + 3 * mapsz + (size_t)b * 4096;
    float* gBase = out + ((size_t)(b * BD + d)) * 4096;

#pragma unroll
    for (int c = 0; c < 4; c++) {
        float* buf = smb + (c & 1) * 3072;
        if (c >= 2) {
            // Slot c&1 was committed at iteration c-2; ensure its smem reads
            // are done (at most 1 group may still be pending: iteration c-1).
            if (tid == 0)
                asm volatile("cp.async.bulk.wait_group.read 1;" ::: "memory");
            __syncthreads();
        }

        int q = c * 256 + tid;            // quad index (4 consecutive cols)
        int4 t4 = tblv[q];
        int i  = q >> 4;
        int j0 = (q & 15) << 2;
        float4* pB = (float4*)buf + tid;
        float4* pL = (float4*)buf + 256 + tid;
        float4* pC = (float4*)buf + 512 + tid;

        if ((t4.x & t4.y & t4.z & t4.w) < 0) {
            float4 z = make_float4(0.f, 0.f, 0.f, 0.f);
            *pB = z; *pL = z; *pC = z;
            if (d == 0) __stcs((float4*)maskp + q, z);
        } else {
            float4 f4 = facv[q];
            float fs[4] = {f4.x, f4.y, f4.z, f4.w};
            int   ts[4] = {t4.x, t4.y, t4.z, t4.w};
            float xi = lev[i];
            float bo[4], lc[4], co[4], mk[4];
#pragma unroll
            for (int cc = 0; cc < 4; cc++) {
                int t = ts[cc];
                if (t < 0) { bo[cc] = 0.f; lc[cc] = 0.f; co[cc] = 0.f; mk[cc] = 0.f; }
                else {
                    int j = j0 + cc;
                    float xj = lev[j];
                    float xk = lev[(i + j) >> 1];
                    float f  = fs[cc];
                    bo[cc] = (xi + xj) * 0.5f * f;
                    lc[cc] = (xi + xj + 0.5f * xk) * (1.f / 2.5f) * f;
                    co[cc] = fmaxf(lev[t & 1023], lev[(t >> 10) & 1023]) * f;
                    mk[cc] = 1.f;
                }
            }
            *pB = make_float4(bo[0], bo[1], bo[2], bo[3]);
            *pL = make_float4(lc[0], lc[1], lc[2], lc[3]);
            *pC = make_float4(co[0], co[1], co[2], co[3]);
            if (d == 0) __stcs((float4*)maskp + q,
                               make_float4(mk[0], mk[1], mk[2], mk[3]));
        }
        __syncthreads();

        if (tid == 0) {
            uint32_t s0;
            asm("{ .reg .u64 t; cvta.to.shared.u64 t, %1; cvt.u32.u64 %0, t; }"
                : "=r"(s0) : "l"(buf));
            asm volatile("fence.proxy.async.shared::cta;" ::: "memory");
            asm volatile("cp.async.bulk.global.shared::cta.bulk_group [%0], [%1], %2;"
                         :: "l"(gBase + c * 1024), "r"(s0), "r"(4096) : "memory");
            asm volatile("cp.async.bulk.global.shared::cta.bulk_group [%0], [%1], %2;"
                         :: "l"(gBase + mapsz + c * 1024), "r"(s0 + 4096), "r"(4096) : "memory");
            asm volatile("cp.async.bulk.global.shared::cta.bulk_group [%0], [%1], %2;"
                         :: "l"(gBase + 2 * mapsz + c * 1024), "r"(s0 + 8192), "r"(4096) : "memory");
            asm volatile("cp.async.bulk.commit_group;" ::: "memory");
        }
    }

    // Keep the CTA (and its smem) alive until all bulk reads complete.
    if (tid == 0)
        asm volatile("cp.async.bulk.wait_group.read 0;" ::: "memory");
}

// ---------------------------------------------------------------------------
extern "C" void kernel_launch(void* const* d_in, const int* in_sizes, int n_in,
                              void* d_out, int out_size) {
    const float* x   = (const float*)d_in[0];
    const float* w_c = (const float*)d_in[1];
    const float* b_c = (const float*)d_in[2];
    const float* w_v = (const float*)d_in[3];
    const float* b_v = (const float*)d_in[4];
    float* out = (float*)d_out;

    gemm_kernel<<<dim3(16, 16), 256>>>(x, w_v, b_v, w_c, b_c);
    attn_kernel<<<dim3(4, 16), 256>>>();
    main_kernel<<<dim3(512, 16), 256, SMEM_MAIN_BYTES>>>(x, out);
}